// round 13
// baseline (speedup 1.0000x reference)
#include <cuda_runtime.h>
#include <math.h>

// Problem capacities (runtime sizes from in_sizes)
#define MAXF 2000000
#define MAXV 500000

// Scratch (allocation-free rule: __device__ globals)
__device__ float4 g_fun[MAXF];   // .x = nom, .y = den, .z = tmp, .w unused
__device__ float4 g_var[MAXV];   // {p, dl, exp(c*p), exp(c*(1-p))}
__device__ double g_acc;
__device__ unsigned int g_ticket;

// One 128-bit vector reduction: 1 RED instead of 3.
__device__ __forceinline__ void red_add_v4(float4* addr, float a, float b, float c)
{
    asm volatile("red.global.add.v4.f32 [%0], {%1, %2, %3, %4};"
                 :: "l"(addr), "f"(a), "f"(b), "f"(c), "f"(0.0f)
                 : "memory");
}

// ---------------------------------------------------------------------------
// Kernel 1: init — zero g_fun (trip~4 coalesced strided loop) and pack
// per-variable {p, dl, e^{c p}, e^{c(1-p)}} (trip~1). Grid sized so each
// thread does ~4 zero stores: amortizes per-thread/block overhead that made
// the one-element-per-thread version issue-bound.
// ---------------------------------------------------------------------------
__global__ void __launch_bounds__(256) init_kernel(
    const float* __restrict__ vp,
    const float* __restrict__ dl,
    const float* __restrict__ gs,
    const float* __restrict__ mc,
    int V, int F)
{
    const float coeff = fminf(sqrtf(__ldg(gs)), __ldg(mc));   // ALPHA = 0.5

    int stride = gridDim.x * blockDim.x;
    int i0 = blockIdx.x * blockDim.x + threadIdx.x;
    if (i0 == 0) { g_acc = 0.0; g_ticket = 0u; }

    const float4 z4 = make_float4(0.0f, 0.0f, 0.0f, 0.0f);
    #pragma unroll 4
    for (int i = i0; i < F; i += stride)
        g_fun[i] = z4;

    for (int i = i0; i < V; i += stride) {
        float p = vp[i];
        float d = dl[i];
        g_var[i] = make_float4(p, d, __expf(coeff * p), __expf(coeff * (1.0f - p)));
    }
}

// ---------------------------------------------------------------------------
// Kernel 2: edge scatter, 8 edges per thread (byte-identical behavior to the
// 92.6us configuration). Value-selects only (no address selection).
//   ef=+1: ev=p,   w=e^{c p},     tl=+dl
//   ef=-1: ev=1-p, w=e^{c(1-p)},  tl=-dl
// ---------------------------------------------------------------------------
__global__ void __launch_bounds__(256) edge_kernel(
    const int*   __restrict__ var_idx,
    const int*   __restrict__ fun_idx,
    const float* __restrict__ ef,
    int E)
{
    const int E8 = E >> 3;
    int stride = gridDim.x * blockDim.x;
    int tid0 = blockIdx.x * blockDim.x + threadIdx.x;

    const int4*   v4p = (const int4*)var_idx;
    const int4*   f4p = (const int4*)fun_idx;
    const float4* e4p = (const float4*)ef;

    for (int i = tid0; i < E8; i += stride) {
        int j = 2 * i;
        int4   v4a = v4p[j],     v4b = v4p[j + 1];
        float4 e4a = e4p[j],     e4b = e4p[j + 1];

        // Issue all 8 gathers first (MLP), then selects + REDs.
        float4 vd[8];
        #pragma unroll
        for (int k = 0; k < 4; k++) vd[k]     = g_var[(&v4a.x)[k]];
        #pragma unroll
        for (int k = 0; k < 4; k++) vd[4 + k] = g_var[(&v4b.x)[k]];

        int4 f4a = f4p[j], f4b = f4p[j + 1];

        #pragma unroll
        for (int k = 0; k < 8; k++) {
            int   f   = (k < 4) ? (&f4a.x)[k] : (&f4b.x)[k - 4];
            float e   = (k < 4) ? (&e4a.x)[k] : (&e4b.x)[k - 4];
            bool  pos = (e > 0.0f);

            float ev = pos ? vd[k].x : (1.0f - vd[k].x);
            float w  = pos ? vd[k].z : vd[k].w;
            float tl = pos ? vd[k].y : -vd[k].y;

            red_add_v4(&g_fun[f], w * ev, w, tl);
        }
    }

    // Tail (E % 8)
    int tail = E8 << 3;
    for (int i = tail + tid0; i < E; i += stride) {
        int    v  = var_idx[i];
        int    f  = fun_idx[i];
        bool  pos = (ef[i] > 0.0f);
        float4 vd = g_var[v];
        float ev = pos ? vd.x : (1.0f - vd.x);
        float w  = pos ? vd.z : vd.w;
        float tl = pos ? vd.y : -vd.y;
        red_add_v4(&g_fun[f], w * ev, w, tl);
    }
}

// ---------------------------------------------------------------------------
// Kernel 3: per-function clause value + mean reduction + finalize.
// Persistent grid; 2 float4 loads in flight per iteration; register-double
// accumulate; one atomic per block; last block (ticket) writes the mean.
// ---------------------------------------------------------------------------
__global__ void __launch_bounds__(256) fun_kernel(
    const float* __restrict__ eps_p,
    const void*  __restrict__ ls_p,
    float* __restrict__ out,
    int F)
{
    // loss_sharpness: defensively decode int-vs-float encoding
    int sharp = 5;
    if (ls_p) {
        int   li = ((const int*)ls_p)[0];
        float lf = ((const float*)ls_p)[0];
        sharp = (li > 0 && li < 1000) ? li : (int)lf;
        if (sharp <= 0 || sharp > 1000) sharp = 5;
    }
    const float eps = eps_p[0];

    double val = 0.0;
    int stride = gridDim.x * blockDim.x;
    int i = blockIdx.x * blockDim.x + threadIdx.x;

    // Process two elements per iteration (two loads in flight).
    for (; i + stride < F; i += 2 * stride) {
        float4 a = g_fun[i];
        float4 b = g_fun[i + stride];

        #pragma unroll
        for (int m = 0; m < 2; m++) {
            float4 c = (m == 0) ? a : b;
            float  n = c.x, d = c.y, t = c.z;

            float cv = d / fmaxf(n, eps);
            float x  = cv - 1.0f;
            float pw;
            if (sharp == 5) {              // fast path: x^5 in 3 mults
                float x2 = x * x;
                pw = x2 * x2 * x;
            } else {
                pw = 1.0f;
                for (int k = 0; k < sharp; k++) pw *= x;
            }
            cv = t * (1.0f + pw);
            val += (double)__logf(fmaxf(fmaxf(cv, 0.0f), eps));
        }
    }
    // Remainder (at most one strided element left for this thread)
    for (; i < F; i += stride) {
        float4 a = g_fun[i];
        float  n = a.x, d = a.y, t = a.z;
        float cv = d / fmaxf(n, eps);
        float x  = cv - 1.0f;
        float pw;
        if (sharp == 5) {
            float x2 = x * x;
            pw = x2 * x2 * x;
        } else {
            pw = 1.0f;
            for (int k = 0; k < sharp; k++) pw *= x;
        }
        cv = t * (1.0f + pw);
        val += (double)__logf(fmaxf(fmaxf(cv, 0.0f), eps));
    }

    // Warp reduction then block reduction (doubles)
    #pragma unroll
    for (int off = 16; off > 0; off >>= 1)
        val += __shfl_down_sync(0xffffffffu, val, off);

    __shared__ double swarp[8];
    int lane = threadIdx.x & 31;
    int wid  = threadIdx.x >> 5;
    if (lane == 0) swarp[wid] = val;
    __syncthreads();
    if (wid == 0) {
        val = (lane < (blockDim.x >> 5)) ? swarp[lane] : 0.0;
        #pragma unroll
        for (int off = 4; off > 0; off >>= 1)
            val += __shfl_down_sync(0xffffffffu, val, off);
        if (lane == 0) {
            atomicAdd(&g_acc, val);
            __threadfence();
            unsigned int t = atomicAdd(&g_ticket, 1u);
            if (t == gridDim.x - 1) {
                out[0] = (float)(g_acc / (double)F);
            }
        }
    }
}

// ---------------------------------------------------------------------------
// Launch. Input order (metadata):
//   0 variable_prediction (V,1) f32
//   1 degree_loss        (V,)  f32
//   2 label              (B,)  f32      [unused]
//   3 graph_map          (2,E) i32      [row0 = var_idx, row1 = fun_idx]
//   4 batch_variable_map (V,)  i32      [unused]
//   5 batch_function_map (F,)  i32      [only shape used: F]
//   6 edge_feature       (E,1) f32
//   7 meta_data          (1,)  f32      [unused]
//   8 global_step        (1,)  f32
//   9 eps                (1,)  f32
//  10 max_coeff          (1,)  f32
//  11 loss_sharpness     scalar
// ---------------------------------------------------------------------------
extern "C" void kernel_launch(void* const* d_in, const int* in_sizes, int n_in,
                              void* d_out, int out_size)
{
    const float* vp   = (const float*)d_in[0];
    const float* dl   = (const float*)d_in[1];
    const int*   gmap = (const int*)  d_in[3];
    const float* ef   = (const float*)d_in[6];
    const float* gs   = (const float*)d_in[8];
    const float* eps  = (const float*)d_in[9];
    const float* mc   = (const float*)d_in[10];
    const void*  ls   = (n_in > 11) ? d_in[11] : nullptr;

    const int V = in_sizes[0];              // number of variables
    const int F = in_sizes[5];              // number of functions (segments)
    const int E = in_sizes[6];              // number of edges
    const int* var_idx = gmap;              // graph_map[0]
    const int* fun_idx = gmap + E;          // graph_map[1]

    float* out = (float*)d_out;

    const int TPB = 256;
    // Zero loop trip ~4, pack loop trip ~1.
    int gridI = (F / 4 + TPB - 1) / TPB;    if (gridI > 8192) gridI = 8192;
    int gridE = ((E >> 3) + TPB - 1) / TPB; if (gridE > 8192) gridE = 8192;
    const int gridFun = 1184;               // 148 SMs * 8 blocks

    init_kernel<<<gridI, TPB>>>(vp, dl, gs, mc, V, F);
    edge_kernel<<<gridE, TPB>>>(var_idx, fun_idx, ef, E);
    fun_kernel<<<gridFun, TPB>>>(eps, ls, out, F);
}

// round 14
// speedup vs baseline: 1.0492x; 1.0492x over previous
#include <cuda_runtime.h>
#include <math.h>

// Problem capacities (runtime sizes from in_sizes)
#define MAXF 2000000
#define MAXV 500000

// Scratch (allocation-free rule: __device__ globals)
__device__ float4 g_fun[MAXF];   // .x = nom, .y = den, .z = tmp, .w unused
__device__ float2 g_vd[MAXV];    // packed {variable_prediction, degree_loss}
__device__ double g_acc;
__device__ unsigned int g_ticket;

// One 128-bit vector reduction: 1 RED instead of 3.
__device__ __forceinline__ void red_add_v4(float4* addr, float a, float b, float c)
{
    asm volatile("red.global.add.v4.f32 [%0], {%1, %2, %3, %4};"
                 :: "l"(addr), "f"(a), "f"(b), "f"(c), "f"(0.0f)
                 : "memory");
}

// ---------------------------------------------------------------------------
// Kernel 1: init — zero g_fun + pack {vp, dl} -> g_vd. NO transcendentals
// (the 1M __expf MUFU floor moved this kernel to ~10us; exp now lives in
// edge_kernel where it hides under the memory shadow).
// ---------------------------------------------------------------------------
__global__ void __launch_bounds__(256) init_kernel(
    const float* __restrict__ vp,
    const float* __restrict__ dl,
    int V, int F)
{
    int stride = gridDim.x * blockDim.x;
    int i0 = blockIdx.x * blockDim.x + threadIdx.x;
    if (i0 == 0) { g_acc = 0.0; g_ticket = 0u; }

    const float4 z4 = make_float4(0.0f, 0.0f, 0.0f, 0.0f);
    for (int i = i0; i < F; i += stride)
        g_fun[i] = z4;
    for (int i = i0; i < V; i += stride)
        g_vd[i] = make_float2(vp[i], dl[i]);
}

// ---------------------------------------------------------------------------
// Kernel 2: edge scatter, 4 edges per thread (R7-exact shape: float2 gather,
// exp computed here, one v4 RED per edge).
// ---------------------------------------------------------------------------
__global__ void __launch_bounds__(256) edge_kernel(
    const int*   __restrict__ var_idx,
    const int*   __restrict__ fun_idx,
    const float* __restrict__ ef,
    const float* __restrict__ gs,
    const float* __restrict__ mc,
    int E)
{
    const float coeff = fminf(sqrtf(__ldg(gs)), __ldg(mc));   // ALPHA = 0.5

    const int E4 = E >> 2;
    int stride = gridDim.x * blockDim.x;
    int tid0 = blockIdx.x * blockDim.x + threadIdx.x;

    const int4*   v4p = (const int4*)var_idx;
    const int4*   f4p = (const int4*)fun_idx;
    const float4* e4p = (const float4*)ef;

    for (int i = tid0; i < E4; i += stride) {
        int4   v4 = v4p[i];
        int4   f4 = f4p[i];
        float4 e4 = e4p[i];

        // Issue all 4 gathers first (MLP), then compute + RED.
        float2 vd[4];
        #pragma unroll
        for (int k = 0; k < 4; k++)
            vd[k] = g_vd[(&v4.x)[k]];

        #pragma unroll
        for (int k = 0; k < 4; k++) {
            int   f = (&f4.x)[k];
            float e = (&e4.x)[k];

            float ev = e * vd[k].x + (1.0f - e) * 0.5f;
            float w  = __expf(coeff * ev);
            float tl = e * vd[k].y;

            red_add_v4(&g_fun[f], w * ev, w, tl);
        }
    }

    // Tail (E % 4)
    int tail = E4 << 2;
    for (int i = tail + tid0; i < E; i += stride) {
        int    v = var_idx[i];
        int    f = fun_idx[i];
        float  e = ef[i];
        float2 p = g_vd[v];
        float ev = e * p.x + (1.0f - e) * 0.5f;
        float w  = __expf(coeff * ev);
        red_add_v4(&g_fun[f], w * ev, w, e * p.y);
    }
}

// ---------------------------------------------------------------------------
// Kernel 3: per-function clause value + mean reduction + finalize.
// Persistent grid; register-double accumulate; one atomic per block; last
// block (ticket) writes the mean. Read-only on g_fun.
// ---------------------------------------------------------------------------
__global__ void __launch_bounds__(256) fun_kernel(
    const float* __restrict__ eps_p,
    const void*  __restrict__ ls_p,
    float* __restrict__ out,
    int F)
{
    // loss_sharpness: defensively decode int-vs-float encoding
    int sharp = 5;
    if (ls_p) {
        int   li = ((const int*)ls_p)[0];
        float lf = ((const float*)ls_p)[0];
        sharp = (li > 0 && li < 1000) ? li : (int)lf;
        if (sharp <= 0 || sharp > 1000) sharp = 5;
    }
    const float eps = eps_p[0];

    double val = 0.0;
    int stride = gridDim.x * blockDim.x;
    for (int i = blockIdx.x * blockDim.x + threadIdx.x; i < F; i += stride) {
        float4 a = g_fun[i];
        float  n = a.x, d = a.y, t = a.z;

        float cv = d / fmaxf(n, eps);
        float x  = cv - 1.0f;
        float pw;
        if (sharp == 5) {                  // fast path: x^5 in 3 mults
            float x2 = x * x;
            pw = x2 * x2 * x;
        } else {
            pw = 1.0f;
            for (int k = 0; k < sharp; k++) pw *= x;
        }
        cv = t * (1.0f + pw);

        // clip(cv, 0) then max(., eps) then log
        val += (double)__logf(fmaxf(fmaxf(cv, 0.0f), eps));
    }

    // Warp reduction then block reduction (doubles)
    #pragma unroll
    for (int off = 16; off > 0; off >>= 1)
        val += __shfl_down_sync(0xffffffffu, val, off);

    __shared__ double swarp[8];
    int lane = threadIdx.x & 31;
    int wid  = threadIdx.x >> 5;
    if (lane == 0) swarp[wid] = val;
    __syncthreads();
    if (wid == 0) {
        val = (lane < (blockDim.x >> 5)) ? swarp[lane] : 0.0;
        #pragma unroll
        for (int off = 4; off > 0; off >>= 1)
            val += __shfl_down_sync(0xffffffffu, val, off);
        if (lane == 0) {
            atomicAdd(&g_acc, val);
            __threadfence();
            unsigned int t = atomicAdd(&g_ticket, 1u);
            if (t == gridDim.x - 1) {
                out[0] = (float)(g_acc / (double)F);
            }
        }
    }
}

// ---------------------------------------------------------------------------
// Launch. Input order (metadata):
//   0 variable_prediction (V,1) f32
//   1 degree_loss        (V,)  f32
//   2 label              (B,)  f32      [unused]
//   3 graph_map          (2,E) i32      [row0 = var_idx, row1 = fun_idx]
//   4 batch_variable_map (V,)  i32      [unused]
//   5 batch_function_map (F,)  i32      [only shape used: F]
//   6 edge_feature       (E,1) f32
//   7 meta_data          (1,)  f32      [unused]
//   8 global_step        (1,)  f32
//   9 eps                (1,)  f32
//  10 max_coeff          (1,)  f32
//  11 loss_sharpness     scalar
// ---------------------------------------------------------------------------
extern "C" void kernel_launch(void* const* d_in, const int* in_sizes, int n_in,
                              void* d_out, int out_size)
{
    const float* vp   = (const float*)d_in[0];
    const float* dl   = (const float*)d_in[1];
    const int*   gmap = (const int*)  d_in[3];
    const float* ef   = (const float*)d_in[6];
    const float* gs   = (const float*)d_in[8];
    const float* eps  = (const float*)d_in[9];
    const float* mc   = (const float*)d_in[10];
    const void*  ls   = (n_in > 11) ? d_in[11] : nullptr;

    const int V = in_sizes[0];              // number of variables
    const int F = in_sizes[5];              // number of functions (segments)
    const int E = in_sizes[6];              // number of edges
    const int* var_idx = gmap;              // graph_map[0]
    const int* fun_idx = gmap + E;          // graph_map[1]

    float* out = (float*)d_out;

    const int TPB = 256;
    int gridI = (F / 4 + TPB - 1) / TPB;    if (gridI > 8192) gridI = 8192;
    int gridE = ((E >> 2) + TPB - 1) / TPB; if (gridE > 8192) gridE = 8192;
    const int gridFun = 1184;               // 148 SMs * 8 blocks

    init_kernel<<<gridI, TPB>>>(vp, dl, V, F);
    edge_kernel<<<gridE, TPB>>>(var_idx, fun_idx, ef, gs, mc, E);
    fun_kernel<<<gridFun, TPB>>>(eps, ls, out, F);
}